// round 3
// baseline (speedup 1.0000x reference)
#include <cuda_runtime.h>

// Problem constants
#define MTOK 32768   // B*T = 64*512
#define DIN  1024
#define DH   512
#define DC   256
#define NC   128

// ---------------- scratch (static device memory; no allocations) ------------
__device__ float g_H[(size_t)MTOK * DH];      // relu(x@W1+b1)   64 MB
__device__ float g_E[(size_t)MTOK * DC];      // encoded         32 MB
__device__ float g_rowNorm[MTOK];             // |e_m|^2
__device__ float g_sqerr[MTOK];               // min_n |e_m - c_n|^2
__device__ float g_cnorm[NC];                 // |c_n|^2

// ---------------- fp32 SGEMM: C = act(A@B + bias) ---------------------------
// BM=BN=128, BK=8, TM=TN=8, 256 threads, double-buffered smem.
// A_FROM_H: A operand is g_H (else the Aext arg). C_TO_H: C is g_H (else g_E).
template<bool RELU, bool A_FROM_H, bool C_TO_H>
__global__ __launch_bounds__(256, 2)
void gemm_bias_kernel(const float* __restrict__ Aext,
                      const float* __restrict__ B,
                      const float* __restrict__ bias,
                      int M, int N, int K)
{
    constexpr int BM = 128, BN = 128, BK = 8, TM = 8, TN = 8;
    __shared__ __align__(16) float As[2][BK][BM];   // transposed A tile
    __shared__ __align__(16) float Bs[2][BK][BN];

    const float* A = A_FROM_H ? (const float*)g_H : Aext;
    float*       C = C_TO_H   ? (float*)g_H       : (float*)g_E;

    const int tid = threadIdx.x;
    const int tx  = tid & 15;          // 0..15 along N
    const int ty  = tid >> 4;          // 0..15 along M
    const int row0 = blockIdx.y * BM;
    const int col0 = blockIdx.x * BN;

    // tile-load index split
    const int arow = tid >> 1;         // 0..127
    const int acol = (tid & 1) * 4;    // 0 or 4
    const int brow = tid >> 5;         // 0..7
    const int bcol = (tid & 31) * 4;   // 0..124

    const float* Aptr = A + (size_t)(row0 + arow) * K + acol;
    const float* Bptr = B + (size_t)brow * N + col0 + bcol;

    // preload k-tile 0
    float4 av = *(const float4*)Aptr;
    float4 bv = *(const float4*)Bptr;
    As[0][acol + 0][arow] = av.x;
    As[0][acol + 1][arow] = av.y;
    As[0][acol + 2][arow] = av.z;
    As[0][acol + 3][arow] = av.w;
    *(float4*)&Bs[0][brow][bcol] = bv;
    __syncthreads();

    float acc[TM][TN] = {};
    const int nk = K / BK;
    int buf = 0;

    for (int kt = 0; kt < nk; ++kt) {
        float4 av2, bv2;
        const bool more = (kt + 1 < nk);
        if (more) {
            av2 = *(const float4*)(Aptr + (kt + 1) * BK);
            bv2 = *(const float4*)(Bptr + (size_t)(kt + 1) * BK * N);
        }
        #pragma unroll
        for (int k = 0; k < BK; ++k) {
            float a[TM], b[TN];
            *(float4*)&a[0] = *(const float4*)&As[buf][k][ty * TM];
            *(float4*)&a[4] = *(const float4*)&As[buf][k][ty * TM + 4];
            *(float4*)&b[0] = *(const float4*)&Bs[buf][k][tx * TN];
            *(float4*)&b[4] = *(const float4*)&Bs[buf][k][tx * TN + 4];
            #pragma unroll
            for (int i = 0; i < TM; ++i)
                #pragma unroll
                for (int j = 0; j < TN; ++j)
                    acc[i][j] = fmaf(a[i], b[j], acc[i][j]);
        }
        if (more) {
            As[buf ^ 1][acol + 0][arow] = av2.x;
            As[buf ^ 1][acol + 1][arow] = av2.y;
            As[buf ^ 1][acol + 2][arow] = av2.z;
            As[buf ^ 1][acol + 3][arow] = av2.w;
            *(float4*)&Bs[buf ^ 1][brow][bcol] = bv2;
            buf ^= 1;
            __syncthreads();
        }
    }

    float bj[TN];
    #pragma unroll
    for (int j = 0; j < TN; ++j) bj[j] = bias[col0 + tx * TN + j];

    #pragma unroll
    for (int i = 0; i < TM; ++i) {
        float tmp[8];
        #pragma unroll
        for (int j = 0; j < TN; ++j) {
            float v = acc[i][j] + bj[j];
            if (RELU) v = fmaxf(v, 0.0f);
            tmp[j] = v;
        }
        float* crow = C + (size_t)(row0 + ty * TM + i) * N + col0 + tx * TN;
        *(float4*)&crow[0] = *(float4*)&tmp[0];
        *(float4*)&crow[4] = *(float4*)&tmp[4];
    }
}

// ---------------- |e_m|^2 : one warp per token row --------------------------
__global__ __launch_bounds__(256)
void rownorm_kernel()
{
    const int gtid = blockIdx.x * blockDim.x + threadIdx.x;
    const int row  = gtid >> 5;
    const int lane = gtid & 31;
    const float4* e = (const float4*)(g_E + (size_t)row * DC);   // 64 float4 / row
    float4 v1 = e[lane];
    float4 v2 = e[lane + 32];
    float s = v1.x * v1.x + v1.y * v1.y + v1.z * v1.z + v1.w * v1.w
            + v2.x * v2.x + v2.y * v2.y + v2.z * v2.z + v2.w * v2.w;
    #pragma unroll
    for (int off = 16; off > 0; off >>= 1)
        s += __shfl_xor_sync(0xffffffffu, s, off);
    if (lane == 0) g_rowNorm[row] = s;
}

// ---------------- |c_n|^2 ----------------------------------------------------
__global__ void cnorm_kernel(const float* __restrict__ cb)
{
    const int n = threadIdx.x;   // 128 threads
    const float4* c = (const float4*)(cb + (size_t)n * DC);
    float s = 0.0f;
    #pragma unroll
    for (int i = 0; i < DC / 4; ++i) {
        float4 v = c[i];
        s += v.x * v.x + v.y * v.y + v.z * v.z + v.w * v.w;
    }
    g_cnorm[n] = s;
}

// ---------------- fused distance GEMM + argmin -------------------------------
// Per block: 128 tokens x all 128 codes. dot = E@cb^T via tiled fp32 GEMM,
// then per-row argmin of (|c|^2 - 2*dot); tie -> lower index (jnp.argmin).
__global__ __launch_bounds__(256, 2)
void argmin_kernel(const float* __restrict__ cb, float* __restrict__ out)
{
    constexpr int BM = 128, BK = 8;
    __shared__ __align__(16) float As[2][BK][BM];
    __shared__ __align__(16) float Bs[2][BK][NC];
    __shared__ float cn[NC];

    const int tid = threadIdx.x;
    const int tx  = tid & 15;
    const int ty  = tid >> 4;
    const int row0 = blockIdx.x * BM;

    if (tid < NC) cn[tid] = g_cnorm[tid];

    const int arow = tid >> 1;
    const int acol = (tid & 1) * 4;
    const int bn   = tid >> 1;        // code index 0..127
    const int bk   = (tid & 1) * 4;   // 0 or 4 within BK

    const float* Aptr = g_E + (size_t)(row0 + arow) * DC + acol;
    const float* Bptr = cb  + (size_t)bn * DC + bk;

    float4 av = *(const float4*)Aptr;
    float4 bv = *(const float4*)Bptr;
    As[0][acol + 0][arow] = av.x;
    As[0][acol + 1][arow] = av.y;
    As[0][acol + 2][arow] = av.z;
    As[0][acol + 3][arow] = av.w;
    Bs[0][bk + 0][bn] = bv.x;
    Bs[0][bk + 1][bn] = bv.y;
    Bs[0][bk + 2][bn] = bv.z;
    Bs[0][bk + 3][bn] = bv.w;
    __syncthreads();

    float acc[8][8] = {};
    const int nk = DC / BK;   // 32
    int buf = 0;
    for (int kt = 0; kt < nk; ++kt) {
        float4 av2, bv2;
        const bool more = (kt + 1 < nk);
        if (more) {
            av2 = *(const float4*)(Aptr + (kt + 1) * BK);
            bv2 = *(const float4*)(Bptr + (kt + 1) * BK);
        }
        #pragma unroll
        for (int k = 0; k < BK; ++k) {
            float a[8], b[8];
            *(float4*)&a[0] = *(const float4*)&As[buf][k][ty * 8];
            *(float4*)&a[4] = *(const float4*)&As[buf][k][ty * 8 + 4];
            *(float4*)&b[0] = *(const float4*)&Bs[buf][k][tx * 8];
            *(float4*)&b[4] = *(const float4*)&Bs[buf][k][tx * 8 + 4];
            #pragma unroll
            for (int i = 0; i < 8; ++i)
                #pragma unroll
                for (int j = 0; j < 8; ++j)
                    acc[i][j] = fmaf(a[i], b[j], acc[i][j]);
        }
        if (more) {
            As[buf ^ 1][acol + 0][arow] = av2.x;
            As[buf ^ 1][acol + 1][arow] = av2.y;
            As[buf ^ 1][acol + 2][arow] = av2.z;
            As[buf ^ 1][acol + 3][arow] = av2.w;
            Bs[buf ^ 1][bk + 0][bn] = bv2.x;
            Bs[buf ^ 1][bk + 1][bn] = bv2.y;
            Bs[buf ^ 1][bk + 2][bn] = bv2.z;
            Bs[buf ^ 1][bk + 3][bn] = bv2.w;
            buf ^= 1;
            __syncthreads();
        }
    }

    // per-row argmin of d2rel = |c|^2 - 2*dot  (row norm is constant per row)
    #pragma unroll
    for (int i = 0; i < 8; ++i) {
        float mv = 3.0e38f;
        int   mi = 0;
        #pragma unroll
        for (int j = 0; j < 8; ++j) {
            float v = cn[tx * 8 + j] - 2.0f * acc[i][j];
            if (v < mv) { mv = v; mi = tx * 8 + j; }
        }
        // reduce across the 16 tx lanes sharing this ty (contiguous 16-lane group)
        #pragma unroll
        for (int off = 8; off >= 1; off >>= 1) {
            float ov = __shfl_xor_sync(0xffffffffu, mv, off);
            int   oi = __shfl_xor_sync(0xffffffffu, mi, off);
            if (ov < mv || (ov == mv && oi < mi)) { mv = ov; mi = oi; }
        }
        if (tx == 0) {
            const int r = row0 + ty * 8 + i;
            out[r]      = (float)mi;                 // token index as f32
            g_sqerr[r]  = g_rowNorm[r] + mv;         // min |e - c|^2
        }
    }
}

// ---------------- deterministic loss reduction -------------------------------
__global__ void reduce_loss_kernel(float* __restrict__ out)
{
    __shared__ double sm[1024];
    const int tid = threadIdx.x;
    double s = 0.0;
    for (int i = tid; i < MTOK; i += 1024) s += (double)g_sqerr[i];
    sm[tid] = s;
    __syncthreads();
    for (int off = 512; off > 0; off >>= 1) {
        if (tid < off) sm[tid] += sm[tid + off];
        __syncthreads();
    }
    if (tid == 0) {
        const float loss = (float)(sm[0] / ((double)MTOK * (double)DC));
        out[MTOK + 0] = loss;          // commitment_loss
        out[MTOK + 1] = loss;          // codebook_loss (identical value)
        out[MTOK + 2] = 1.25f * loss;  // total_loss
    }
}

// ---------------- launch ------------------------------------------------------
extern "C" void kernel_launch(void* const* d_in, const int* in_sizes, int n_in,
                              void* d_out, int out_size)
{
    const float* x  = (const float*)d_in[0];   // [64,512,1024]
    const float* W1 = (const float*)d_in[1];   // [1024,512]
    const float* b1 = (const float*)d_in[2];   // [512]
    const float* W2 = (const float*)d_in[3];   // [512,256]
    const float* b2 = (const float*)d_in[4];   // [256]
    const float* cb = (const float*)d_in[5];   // [128,256]
    // d_in[6], d_in[7] (Wd, bd) feed dead code in the reference -> unused.
    float* out = (float*)d_out;                // [32768 idx | 3 losses]

    // GEMM1: H = relu(x@W1 + b1)
    gemm_bias_kernel<true,  false, true ><<<dim3(DH / 128, MTOK / 128), 256>>>(
        x, W1, b1, MTOK, DH, DIN);
    // GEMM2: E = H@W2 + b2
    gemm_bias_kernel<false, true,  false><<<dim3(DC / 128, MTOK / 128), 256>>>(
        nullptr, W2, b2, MTOK, DC, DH);
    // row norms |e|^2 (one warp per row)
    rownorm_kernel<<<MTOK / 8, 256>>>();
    // codebook norms |c|^2
    cnorm_kernel<<<1, NC>>>(cb);
    // distances + argmin + per-token squared error
    argmin_kernel<<<MTOK / 128, 256>>>(cb, out);
    // losses
    reduce_loss_kernel<<<1, 1024>>>(out);
}

// round 4
// speedup vs baseline: 1.0012x; 1.0012x over previous
#include <cuda_runtime.h>

// Problem constants
#define MTOK 32768   // B*T = 64*512
#define DIN  1024
#define DH   512
#define DC   256
#define NC   128

// ---------------- scratch (static device memory; no allocations) ------------
__device__ float g_H[(size_t)MTOK * DH];      // relu(x@W1+b1)   64 MB
__device__ float g_E[(size_t)MTOK * DC];      // encoded         32 MB
__device__ float g_rowNorm[MTOK];             // |e_m|^2
__device__ float g_sqerr[MTOK];               // min_n |e_m - c_n|^2
__device__ float g_cnorm[NC];                 // |c_n|^2

// ---------------- fp32 SGEMM: C = act(A@B + bias) ---------------------------
// BM=BN=128, BK=8, TM=TN=8, 256 threads, double-buffered smem.
// A_FROM_H: A operand is g_H (else the Aext arg). C_TO_H: C is g_H (else g_E).
template<bool RELU, bool A_FROM_H, bool C_TO_H>
__global__ __launch_bounds__(256, 2)
void gemm_bias_kernel(const float* __restrict__ Aext,
                      const float* __restrict__ B,
                      const float* __restrict__ bias,
                      int M, int N, int K)
{
    constexpr int BM = 128, BN = 128, BK = 8, TM = 8, TN = 8;
    __shared__ __align__(16) float As[2][BK][BM];   // transposed A tile
    __shared__ __align__(16) float Bs[2][BK][BN];

    const float* A = A_FROM_H ? (const float*)g_H : Aext;
    float*       C = C_TO_H   ? (float*)g_H       : (float*)g_E;

    const int tid = threadIdx.x;
    const int tx  = tid & 15;          // 0..15 along N
    const int ty  = tid >> 4;          // 0..15 along M
    const int row0 = blockIdx.y * BM;
    const int col0 = blockIdx.x * BN;

    // tile-load index split
    const int arow = tid >> 1;         // 0..127
    const int acol = (tid & 1) * 4;    // 0 or 4
    const int brow = tid >> 5;         // 0..7
    const int bcol = (tid & 31) * 4;   // 0..124

    const float* Aptr = A + (size_t)(row0 + arow) * K + acol;
    const float* Bptr = B + (size_t)brow * N + col0 + bcol;

    // preload k-tile 0
    float4 av = *(const float4*)Aptr;
    float4 bv = *(const float4*)Bptr;
    As[0][acol + 0][arow] = av.x;
    As[0][acol + 1][arow] = av.y;
    As[0][acol + 2][arow] = av.z;
    As[0][acol + 3][arow] = av.w;
    *(float4*)&Bs[0][brow][bcol] = bv;
    __syncthreads();

    float acc[TM][TN] = {};
    const int nk = K / BK;
    int buf = 0;

    for (int kt = 0; kt < nk; ++kt) {
        float4 av2, bv2;
        const bool more = (kt + 1 < nk);
        if (more) {
            av2 = *(const float4*)(Aptr + (kt + 1) * BK);
            bv2 = *(const float4*)(Bptr + (size_t)(kt + 1) * BK * N);
        }
        #pragma unroll
        for (int k = 0; k < BK; ++k) {
            float a[TM], b[TN];
            *(float4*)&a[0] = *(const float4*)&As[buf][k][ty * TM];
            *(float4*)&a[4] = *(const float4*)&As[buf][k][ty * TM + 4];
            *(float4*)&b[0] = *(const float4*)&Bs[buf][k][tx * TN];
            *(float4*)&b[4] = *(const float4*)&Bs[buf][k][tx * TN + 4];
            #pragma unroll
            for (int i = 0; i < TM; ++i)
                #pragma unroll
                for (int j = 0; j < TN; ++j)
                    acc[i][j] = fmaf(a[i], b[j], acc[i][j]);
        }
        if (more) {
            As[buf ^ 1][acol + 0][arow] = av2.x;
            As[buf ^ 1][acol + 1][arow] = av2.y;
            As[buf ^ 1][acol + 2][arow] = av2.z;
            As[buf ^ 1][acol + 3][arow] = av2.w;
            *(float4*)&Bs[buf ^ 1][brow][bcol] = bv2;
            buf ^= 1;
            __syncthreads();
        }
    }

    float bj[TN];
    #pragma unroll
    for (int j = 0; j < TN; ++j) bj[j] = bias[col0 + tx * TN + j];

    #pragma unroll
    for (int i = 0; i < TM; ++i) {
        float tmp[8];
        #pragma unroll
        for (int j = 0; j < TN; ++j) {
            float v = acc[i][j] + bj[j];
            if (RELU) v = fmaxf(v, 0.0f);
            tmp[j] = v;
        }
        float* crow = C + (size_t)(row0 + ty * TM + i) * N + col0 + tx * TN;
        *(float4*)&crow[0] = *(float4*)&tmp[0];
        *(float4*)&crow[4] = *(float4*)&tmp[4];
    }
}

// ---------------- |e_m|^2 : one warp per token row --------------------------
__global__ __launch_bounds__(256)
void rownorm_kernel()
{
    const int gtid = blockIdx.x * blockDim.x + threadIdx.x;
    const int row  = gtid >> 5;
    const int lane = gtid & 31;
    const float4* e = (const float4*)(g_E + (size_t)row * DC);   // 64 float4 / row
    float4 v1 = e[lane];
    float4 v2 = e[lane + 32];
    float s = v1.x * v1.x + v1.y * v1.y + v1.z * v1.z + v1.w * v1.w
            + v2.x * v2.x + v2.y * v2.y + v2.z * v2.z + v2.w * v2.w;
    #pragma unroll
    for (int off = 16; off > 0; off >>= 1)
        s += __shfl_xor_sync(0xffffffffu, s, off);
    if (lane == 0) g_rowNorm[row] = s;
}

// ---------------- |c_n|^2 ----------------------------------------------------
__global__ void cnorm_kernel(const float* __restrict__ cb)
{
    const int n = threadIdx.x;   // 128 threads
    const float4* c = (const float4*)(cb + (size_t)n * DC);
    float s = 0.0f;
    #pragma unroll
    for (int i = 0; i < DC / 4; ++i) {
        float4 v = c[i];
        s += v.x * v.x + v.y * v.y + v.z * v.z + v.w * v.w;
    }
    g_cnorm[n] = s;
}

// ---------------- fused distance GEMM + argmin -------------------------------
// Per block: 128 tokens x all 128 codes. dot = E@cb^T via tiled fp32 GEMM,
// then per-row argmin of (|c|^2 - 2*dot); tie -> lower index (jnp.argmin).
__global__ __launch_bounds__(256, 2)
void argmin_kernel(const float* __restrict__ cb, float* __restrict__ out)
{
    constexpr int BM = 128, BK = 8;
    __shared__ __align__(16) float As[2][BK][BM];
    __shared__ __align__(16) float Bs[2][BK][NC];
    __shared__ float cn[NC];

    const int tid = threadIdx.x;
    const int tx  = tid & 15;
    const int ty  = tid >> 4;
    const int row0 = blockIdx.x * BM;

    if (tid < NC) cn[tid] = g_cnorm[tid];

    const int arow = tid >> 1;
    const int acol = (tid & 1) * 4;
    const int bn   = tid >> 1;        // code index 0..127
    const int bk   = (tid & 1) * 4;   // 0 or 4 within BK

    const float* Aptr = g_E + (size_t)(row0 + arow) * DC + acol;
    const float* Bptr = cb  + (size_t)bn * DC + bk;

    float4 av = *(const float4*)Aptr;
    float4 bv = *(const float4*)Bptr;
    As[0][acol + 0][arow] = av.x;
    As[0][acol + 1][arow] = av.y;
    As[0][acol + 2][arow] = av.z;
    As[0][acol + 3][arow] = av.w;
    Bs[0][bk + 0][bn] = bv.x;
    Bs[0][bk + 1][bn] = bv.y;
    Bs[0][bk + 2][bn] = bv.z;
    Bs[0][bk + 3][bn] = bv.w;
    __syncthreads();

    float acc[8][8] = {};
    const int nk = DC / BK;   // 32
    int buf = 0;
    for (int kt = 0; kt < nk; ++kt) {
        float4 av2, bv2;
        const bool more = (kt + 1 < nk);
        if (more) {
            av2 = *(const float4*)(Aptr + (kt + 1) * BK);
            bv2 = *(const float4*)(Bptr + (kt + 1) * BK);
        }
        #pragma unroll
        for (int k = 0; k < BK; ++k) {
            float a[8], b[8];
            *(float4*)&a[0] = *(const float4*)&As[buf][k][ty * 8];
            *(float4*)&a[4] = *(const float4*)&As[buf][k][ty * 8 + 4];
            *(float4*)&b[0] = *(const float4*)&Bs[buf][k][tx * 8];
            *(float4*)&b[4] = *(const float4*)&Bs[buf][k][tx * 8 + 4];
            #pragma unroll
            for (int i = 0; i < 8; ++i)
                #pragma unroll
                for (int j = 0; j < 8; ++j)
                    acc[i][j] = fmaf(a[i], b[j], acc[i][j]);
        }
        if (more) {
            As[buf ^ 1][acol + 0][arow] = av2.x;
            As[buf ^ 1][acol + 1][arow] = av2.y;
            As[buf ^ 1][acol + 2][arow] = av2.z;
            As[buf ^ 1][acol + 3][arow] = av2.w;
            Bs[buf ^ 1][bk + 0][bn] = bv2.x;
            Bs[buf ^ 1][bk + 1][bn] = bv2.y;
            Bs[buf ^ 1][bk + 2][bn] = bv2.z;
            Bs[buf ^ 1][bk + 3][bn] = bv2.w;
            buf ^= 1;
            __syncthreads();
        }
    }

    // per-row argmin of d2rel = |c|^2 - 2*dot  (row norm is constant per row)
    #pragma unroll
    for (int i = 0; i < 8; ++i) {
        float mv = 3.0e38f;
        int   mi = 0;
        #pragma unroll
        for (int j = 0; j < 8; ++j) {
            float v = cn[tx * 8 + j] - 2.0f * acc[i][j];
            if (v < mv) { mv = v; mi = tx * 8 + j; }
        }
        // reduce across the 16 tx lanes sharing this ty (contiguous 16-lane group)
        #pragma unroll
        for (int off = 8; off >= 1; off >>= 1) {
            float ov = __shfl_xor_sync(0xffffffffu, mv, off);
            int   oi = __shfl_xor_sync(0xffffffffu, mi, off);
            if (ov < mv || (ov == mv && oi < mi)) { mv = ov; mi = oi; }
        }
        if (tx == 0) {
            const int r = row0 + ty * 8 + i;
            out[r]      = (float)mi;                 // token index as f32
            g_sqerr[r]  = g_rowNorm[r] + mv;         // min |e - c|^2
        }
    }
}

// ---------------- deterministic loss reduction -------------------------------
__global__ void reduce_loss_kernel(float* __restrict__ out)
{
    __shared__ double sm[1024];
    const int tid = threadIdx.x;
    double s = 0.0;
    for (int i = tid; i < MTOK; i += 1024) s += (double)g_sqerr[i];
    sm[tid] = s;
    __syncthreads();
    for (int off = 512; off > 0; off >>= 1) {
        if (tid < off) sm[tid] += sm[tid + off];
        __syncthreads();
    }
    if (tid == 0) {
        const float loss = (float)(sm[0] / ((double)MTOK * (double)DC));
        out[MTOK + 0] = loss;          // commitment_loss
        out[MTOK + 1] = loss;          // codebook_loss (identical value)
        out[MTOK + 2] = 1.25f * loss;  // total_loss
    }
}

// ---------------- launch ------------------------------------------------------
extern "C" void kernel_launch(void* const* d_in, const int* in_sizes, int n_in,
                              void* d_out, int out_size)
{
    const float* x  = (const float*)d_in[0];   // [64,512,1024]
    const float* W1 = (const float*)d_in[1];   // [1024,512]
    const float* b1 = (const float*)d_in[2];   // [512]
    const float* W2 = (const float*)d_in[3];   // [512,256]
    const float* b2 = (const float*)d_in[4];   // [256]
    const float* cb = (const float*)d_in[5];   // [128,256]
    // d_in[6], d_in[7] (Wd, bd) feed dead code in the reference -> unused.
    float* out = (float*)d_out;                // [32768 idx | 3 losses]

    // GEMM1: H = relu(x@W1 + b1)
    gemm_bias_kernel<true,  false, true ><<<dim3(DH / 128, MTOK / 128), 256>>>(
        x, W1, b1, MTOK, DH, DIN);
    // GEMM2: E = H@W2 + b2
    gemm_bias_kernel<false, true,  false><<<dim3(DC / 128, MTOK / 128), 256>>>(
        nullptr, W2, b2, MTOK, DC, DH);
    // row norms |e|^2 (one warp per row)
    rownorm_kernel<<<MTOK / 8, 256>>>();
    // codebook norms |c|^2
    cnorm_kernel<<<1, NC>>>(cb);
    // distances + argmin + per-token squared error
    argmin_kernel<<<MTOK / 128, 256>>>(cb, out);
    // losses
    reduce_loss_kernel<<<1, 1024>>>(out);
}

// round 6
// speedup vs baseline: 1.2907x; 1.2891x over previous
#include <cuda_runtime.h>
#include <cstdint>

#define MTOK 32768
#define DIN  1024
#define DH   512
#define DC   256
#define NC   128

// ---------------- scratch (static device memory) ----------------------------
__device__ float g_H[(size_t)MTOK * DH];
__device__ float g_E[(size_t)MTOK * DC];
__device__ float g_rowNorm[MTOK];
__device__ float g_sqerr[MTOK];
__device__ float g_cnorm[NC];

// ---------------- helpers -----------------------------------------------------
__device__ __forceinline__ void mma_tf32(float* d, const uint32_t* a, const uint32_t* b) {
    asm volatile(
        "mma.sync.aligned.m16n8k8.row.col.f32.tf32.tf32.f32 "
        "{%0,%1,%2,%3}, {%4,%5,%6,%7}, {%8,%9}, {%0,%1,%2,%3};"
        : "+f"(d[0]), "+f"(d[1]), "+f"(d[2]), "+f"(d[3])
        : "r"(a[0]), "r"(a[1]), "r"(a[2]), "r"(a[3]), "r"(b[0]), "r"(b[1]));
}
// split v = hi + lo; hi exactly representable in tf32, lo rounded (rna) to tf32
__device__ __forceinline__ void split_tf32(float v, uint32_t& hi, uint32_t& lo) {
    uint32_t h = __float_as_uint(v) & 0xFFFFE000u;
    float l = v - __uint_as_float(h);
    uint32_t lr;
    asm("cvt.rna.tf32.f32 %0, %1;" : "=r"(lr) : "f"(l));
    hi = h; lo = lr;
}

// ==================== 3xTF32 mma.sync GEMM: C = act(A@B + bias) ==============
// A [M,K] row-major, B [K,N] row-major. BM=128, BN=128, BK=16.
// 256 threads, 8 warps in 2x4; warp tile 64x32 = 4x4 (m16n8) mma tiles.
#define AS_STR 136

template<bool RELU>
__global__ __launch_bounds__(256)
void gemm_mma(const float* __restrict__ A, const float* __restrict__ B,
              const float* __restrict__ bias, float* __restrict__ C,
              int N, int K)
{
    __shared__ float As[2][16][AS_STR];
    __shared__ float Bs[2][16][AS_STR];

    const int tid  = threadIdx.x;
    const int wid  = tid >> 5;
    const int lane = tid & 31;
    const int quad = lane & 3;        // k offset within frag
    const int qrow = lane >> 2;       // row/col offset within frag

    const int row0 = blockIdx.y * 128;
    const int col0 = blockIdx.x * 128;
    const int wm0  = (wid >> 2) * 64;   // warp m offset (0 or 64)
    const int wn0  = (wid & 3) * 32;    // warp n offset (0,32,64,96)

    // global load indexing
    const int arow = tid >> 1;               // 0..127
    const int acol = (tid & 1) * 8;          // 0 or 8
    const float* Aptr = A + (size_t)(row0 + arow) * K + acol;
    const int br0 = tid >> 5;                // 0..7  (B rows, first half)
    const int bc0 = (tid & 31) * 4;          // 0..124
    const float* Bp0 = B + (size_t)br0 * N + col0 + bc0;
    const float* Bp1 = B + (size_t)(br0 + 8) * N + col0 + bc0;

    // ---- preload k-tile 0 ----
    float4 a0 = *(const float4*)Aptr;
    float4 a1 = *(const float4*)(Aptr + 4);
    float4 b0 = *(const float4*)Bp0;
    float4 b1 = *(const float4*)Bp1;
    {
        float av0[4] = {a0.x, a0.y, a0.z, a0.w};
        float av1[4] = {a1.x, a1.y, a1.z, a1.w};
        #pragma unroll
        for (int i = 0; i < 4; ++i) {
            As[0][acol + i][arow]     = av0[i];
            As[0][acol + 4 + i][arow] = av1[i];
        }
        *(float4*)&Bs[0][br0][bc0]     = b0;
        *(float4*)&Bs[0][br0 + 8][bc0] = b1;
    }
    __syncthreads();

    float acc[4][4][4] = {};
    const int NK = K >> 4;
    int buf = 0;

    for (int kt = 0; kt < NK; ++kt) {
        const bool more = (kt + 1 < NK);
        if (more) {
            const int k0 = (kt + 1) * 16;
            a0 = *(const float4*)(Aptr + k0);
            a1 = *(const float4*)(Aptr + k0 + 4);
            b0 = *(const float4*)(Bp0 + (size_t)k0 * N);
            b1 = *(const float4*)(Bp1 + (size_t)k0 * N);
        }
        // ---- compute on buf ----
        #pragma unroll
        for (int k8 = 0; k8 < 16; k8 += 8) {
            uint32_t bhi[4][2], blo[4][2];
            #pragma unroll
            for (int u = 0; u < 4; ++u) {
                const int nn = wn0 + 8 * u + qrow;
                split_tf32(Bs[buf][k8 + quad][nn],     bhi[u][0], blo[u][0]);
                split_tf32(Bs[buf][k8 + quad + 4][nn], bhi[u][1], blo[u][1]);
            }
            #pragma unroll
            for (int t = 0; t < 4; ++t) {
                const int mi = wm0 + 16 * t + qrow;
                uint32_t ahi[4], alo[4];
                split_tf32(As[buf][k8 + quad][mi],         ahi[0], alo[0]);
                split_tf32(As[buf][k8 + quad][mi + 8],     ahi[1], alo[1]);
                split_tf32(As[buf][k8 + quad + 4][mi],     ahi[2], alo[2]);
                split_tf32(As[buf][k8 + quad + 4][mi + 8], ahi[3], alo[3]);
                #pragma unroll
                for (int u = 0; u < 4; ++u) {
                    mma_tf32(acc[t][u], ahi, blo[u]);   // small terms first
                    mma_tf32(acc[t][u], alo, bhi[u]);
                    mma_tf32(acc[t][u], ahi, bhi[u]);
                }
            }
        }
        // ---- publish next tile ----
        if (more) {
            float av0[4] = {a0.x, a0.y, a0.z, a0.w};
            float av1[4] = {a1.x, a1.y, a1.z, a1.w};
            #pragma unroll
            for (int i = 0; i < 4; ++i) {
                As[buf ^ 1][acol + i][arow]     = av0[i];
                As[buf ^ 1][acol + 4 + i][arow] = av1[i];
            }
            *(float4*)&Bs[buf ^ 1][br0][bc0]     = b0;
            *(float4*)&Bs[buf ^ 1][br0 + 8][bc0] = b1;
            __syncthreads();
            buf ^= 1;
        }
    }

    // ---- epilogue: bias (+ReLU), store fp32 ----
    #pragma unroll
    for (int u = 0; u < 4; ++u) {
        const int c = col0 + wn0 + 8 * u + 2 * quad;
        const float bj0 = bias[c], bj1 = bias[c + 1];
        #pragma unroll
        for (int t = 0; t < 4; ++t) {
            const int r0 = row0 + wm0 + 16 * t + qrow;
            float v00 = acc[t][u][0] + bj0;
            float v01 = acc[t][u][1] + bj1;
            float v10 = acc[t][u][2] + bj0;
            float v11 = acc[t][u][3] + bj1;
            if (RELU) {
                v00 = fmaxf(v00, 0.0f); v01 = fmaxf(v01, 0.0f);
                v10 = fmaxf(v10, 0.0f); v11 = fmaxf(v11, 0.0f);
            }
            float2 p0 = make_float2(v00, v01);
            float2 p1 = make_float2(v10, v11);
            *(float2*)(C + (size_t)r0 * N + c)       = p0;
            *(float2*)(C + (size_t)(r0 + 8) * N + c) = p1;
        }
    }
}

// ---------------- |e_m|^2 : one warp per token row ---------------------------
__global__ __launch_bounds__(256)
void rownorm_kernel()
{
    const int gtid = blockIdx.x * blockDim.x + threadIdx.x;
    const int row  = gtid >> 5;
    const int lane = gtid & 31;
    const float4* e = (const float4*)(g_E + (size_t)row * DC);
    float4 v1 = e[lane];
    float4 v2 = e[lane + 32];
    float s = v1.x * v1.x + v1.y * v1.y + v1.z * v1.z + v1.w * v1.w
            + v2.x * v2.x + v2.y * v2.y + v2.z * v2.z + v2.w * v2.w;
    #pragma unroll
    for (int off = 16; off > 0; off >>= 1)
        s += __shfl_xor_sync(0xffffffffu, s, off);
    if (lane == 0) g_rowNorm[row] = s;
}

// ---------------- |c_n|^2 : one warp per code ---------------------------------
__global__ void cnorm_kernel(const float* __restrict__ cb)
{
    const int n    = blockIdx.x;
    const int lane = threadIdx.x;
    const float4* c = (const float4*)(cb + (size_t)n * DC);
    float4 v1 = c[lane];
    float4 v2 = c[lane + 32];
    float s = v1.x * v1.x + v1.y * v1.y + v1.z * v1.z + v1.w * v1.w
            + v2.x * v2.x + v2.y * v2.y + v2.z * v2.z + v2.w * v2.w;
    #pragma unroll
    for (int off = 16; off > 0; off >>= 1)
        s += __shfl_xor_sync(0xffffffffu, s, off);
    if (lane == 0) g_cnorm[n] = s;
}

// ---------------- fused distance GEMM + argmin (fp32, exact) ------------------
__global__ __launch_bounds__(256, 2)
void argmin_kernel(const float* __restrict__ cb, float* __restrict__ out)
{
    constexpr int BM = 128, BK = 8;
    __shared__ __align__(16) float As[2][BK][BM];
    __shared__ __align__(16) float Bs[2][BK][NC];
    __shared__ float cn[NC];

    const int tid = threadIdx.x;
    const int tx  = tid & 15;
    const int ty  = tid >> 4;
    const int row0 = blockIdx.x * BM;

    if (tid < NC) cn[tid] = g_cnorm[tid];

    const int arow = tid >> 1;
    const int acol = (tid & 1) * 4;
    const int bn   = tid >> 1;
    const int bk   = (tid & 1) * 4;

    const float* Aptr = g_E + (size_t)(row0 + arow) * DC + acol;
    const float* Bptr = cb  + (size_t)bn * DC + bk;

    float4 av = *(const float4*)Aptr;
    float4 bv = *(const float4*)Bptr;
    As[0][acol + 0][arow] = av.x;
    As[0][acol + 1][arow] = av.y;
    As[0][acol + 2][arow] = av.z;
    As[0][acol + 3][arow] = av.w;
    Bs[0][bk + 0][bn] = bv.x;
    Bs[0][bk + 1][bn] = bv.y;
    Bs[0][bk + 2][bn] = bv.z;
    Bs[0][bk + 3][bn] = bv.w;
    __syncthreads();

    float acc[8][8] = {};
    const int nk = DC / BK;
    int buf = 0;
    for (int kt = 0; kt < nk; ++kt) {
        float4 av2, bv2;
        const bool more = (kt + 1 < nk);
        if (more) {
            av2 = *(const float4*)(Aptr + (kt + 1) * BK);
            bv2 = *(const float4*)(Bptr + (kt + 1) * BK);
        }
        #pragma unroll
        for (int k = 0; k < BK; ++k) {
            float a[8], b[8];
            *(float4*)&a[0] = *(const float4*)&As[buf][k][ty * 8];
            *(float4*)&a[4] = *(const float4*)&As[buf][k][ty * 8 + 4];
            *(float4*)&b[0] = *(const float4*)&Bs[buf][k][tx * 8];
            *(float4*)&b[4] = *(const float4*)&Bs[buf][k][tx * 8 + 4];
            #pragma unroll
            for (int i = 0; i < 8; ++i)
                #pragma unroll
                for (int j = 0; j < 8; ++j)
                    acc[i][j] = fmaf(a[i], b[j], acc[i][j]);
        }
        if (more) {
            As[buf ^ 1][acol + 0][arow] = av2.x;
            As[buf ^ 1][acol + 1][arow] = av2.y;
            As[buf ^ 1][acol + 2][arow] = av2.z;
            As[buf ^ 1][acol + 3][arow] = av2.w;
            Bs[buf ^ 1][bk + 0][bn] = bv2.x;
            Bs[buf ^ 1][bk + 1][bn] = bv2.y;
            Bs[buf ^ 1][bk + 2][bn] = bv2.z;
            Bs[buf ^ 1][bk + 3][bn] = bv2.w;
            buf ^= 1;
            __syncthreads();
        }
    }

    #pragma unroll
    for (int i = 0; i < 8; ++i) {
        float mv = 3.0e38f;
        int   mi = 0;
        #pragma unroll
        for (int j = 0; j < 8; ++j) {
            float v = cn[tx * 8 + j] - 2.0f * acc[i][j];
            if (v < mv) { mv = v; mi = tx * 8 + j; }
        }
        #pragma unroll
        for (int off = 8; off >= 1; off >>= 1) {
            float ov = __shfl_xor_sync(0xffffffffu, mv, off);
            int   oi = __shfl_xor_sync(0xffffffffu, mi, off);
            if (ov < mv || (ov == mv && oi < mi)) { mv = ov; mi = oi; }
        }
        if (tx == 0) {
            const int r = row0 + ty * 8 + i;
            out[r]      = (float)mi;
            g_sqerr[r]  = g_rowNorm[r] + mv;
        }
    }
}

// ---------------- deterministic loss reduction --------------------------------
__global__ void reduce_loss_kernel(float* __restrict__ out)
{
    __shared__ double sm[1024];
    const int tid = threadIdx.x;
    double s = 0.0;
    for (int i = tid; i < MTOK; i += 1024) s += (double)g_sqerr[i];
    sm[tid] = s;
    __syncthreads();
    for (int off = 512; off > 0; off >>= 1) {
        if (tid < off) sm[tid] += sm[tid + off];
        __syncthreads();
    }
    if (tid == 0) {
        const float loss = (float)(sm[0] / ((double)MTOK * (double)DC));
        out[MTOK + 0] = loss;
        out[MTOK + 1] = loss;
        out[MTOK + 2] = 1.25f * loss;
    }
}

// ---------------- launch -------------------------------------------------------
extern "C" void kernel_launch(void* const* d_in, const int* in_sizes, int n_in,
                              void* d_out, int out_size)
{
    const float* x  = (const float*)d_in[0];   // [64,512,1024]
    const float* W1 = (const float*)d_in[1];   // [1024,512]
    const float* b1 = (const float*)d_in[2];   // [512]
    const float* W2 = (const float*)d_in[3];   // [512,256]
    const float* b2 = (const float*)d_in[4];   // [256]
    const float* cb = (const float*)d_in[5];   // [128,256]
    float* out = (float*)d_out;                // [32768 idx | 3 losses]

    float* H = (float*)0; float* E = (float*)0;
    cudaGetSymbolAddress((void**)&H, g_H);
    cudaGetSymbolAddress((void**)&E, g_E);

    // GEMM1: H = relu(x@W1 + b1)
    gemm_mma<true ><<<dim3(DH / 128, MTOK / 128), 256>>>(x, W1, b1, H, DH, DIN);
    // GEMM2: E = H@W2 + b2
    gemm_mma<false><<<dim3(DC / 128, MTOK / 128), 256>>>(H, W2, b2, E, DC, DH);
    // row norms |e|^2
    rownorm_kernel<<<MTOK / 8, 256>>>();
    // codebook norms |c|^2
    cnorm_kernel<<<NC, 32>>>(cb);
    // distances + argmin
    argmin_kernel<<<MTOK / 128, 256>>>(cb, out);
    // losses
    reduce_loss_kernel<<<1, 1024>>>(out);
}